// round 1
// baseline (speedup 1.0000x reference)
#include <cuda_runtime.h>
#include <math.h>

// Problem shape (fixed by dataset): N = 100000 nodes, E = 3200000 edges.
// Scratch: packed per-node accumulator [Z, sumL, sumQ0..3, pad, pad] = 8 floats (32B).
#define MAXN 131072
__device__ float4 g_acc[MAXN * 2];   // node i -> g_acc[2i] = (Z, sumL, q0, q1), g_acc[2i+1] = (q2, q3, -, -)

#define TEMP 10.0f

// ---------------------------------------------------------------------------
// Kernel 1: initialize accumulators with the self term.
//   es = exp(TEMP * l);  Z = es;  sumL = es*l;  sumQ = es*q
// ---------------------------------------------------------------------------
__global__ void init_kernel(const float* __restrict__ node_levels,
                            const float4* __restrict__ node_q,
                            int N) {
    int i = blockIdx.x * blockDim.x + threadIdx.x;
    if (i >= N) return;
    float l = node_levels[i];
    float4 q = node_q[i];
    float es = __expf(TEMP * l);
    g_acc[2 * i]     = make_float4(es, es * l, es * q.x, es * q.y);
    g_acc[2 * i + 1] = make_float4(es * q.z, es * q.w, 0.f, 0.f);
}

// ---------------------------------------------------------------------------
// Kernel 2: per-edge scatter.
//   accu_q = qmul(rel_q, q_src);  ex = exp(TEMP * w * l_src)
//   atomically accumulate (ex, ex*l_src, ex*accu_q) into g_acc[dst]
// Logits are bounded in [0, 10) so the stable-softmax max subtraction cancels
// exactly in the final ratios and is omitted.
// ---------------------------------------------------------------------------
__global__ void edge_kernel(const float* __restrict__ node_levels,
                            const float4* __restrict__ node_q,
                            const float4* __restrict__ edge_rel_q,
                            const float* __restrict__ edge_w,
                            const int* __restrict__ src,
                            const int* __restrict__ dst,
                            int E) {
    int e = blockIdx.x * blockDim.x + threadIdx.x;
    if (e >= E) return;

    int s = __ldg(&src[e]);
    int d = __ldg(&dst[e]);
    float4 a = __ldg(&edge_rel_q[e]);   // rel_q: (w,x,y,z) = (a.x, a.y, a.z, a.w)
    float w  = __ldg(&edge_w[e]);

    float4 b = __ldg(&node_q[s]);       // q_src
    float l  = __ldg(&node_levels[s]);

    // Hamilton product: rel_q * q_src ; components named (w,x,y,z)
    float aw = a.x, ax = a.y, ay = a.z, az = a.w;
    float bw = b.x, bx = b.y, by = b.z, bz = b.w;
    float cw = aw * bw - ax * bx - ay * by - az * bz;
    float cx = aw * bx + ax * bw + ay * bz - az * by;
    float cy = aw * by - ax * bz + ay * bw + az * bx;
    float cz = aw * bz + ax * by - ay * bx + az * bw;

    float ex = __expf(TEMP * w * l);

    float* acc = (float*)&g_acc[2 * d];
    atomicAdd(acc + 0, ex);
    atomicAdd(acc + 1, ex * l);
    atomicAdd(acc + 2, ex * cw);
    atomicAdd(acc + 3, ex * cx);
    atomicAdd(acc + 4, ex * cy);
    atomicAdd(acc + 5, ex * cz);
}

// ---------------------------------------------------------------------------
// Kernel 3: finalize.
//   out_q = normalize(sum_q / Z)   (eps clamp 1e-12)
//   out_levels = sum_l / Z
// Output layout: out[0 .. 4N) = out_q row-major, out[4N .. 5N) = out_levels
// ---------------------------------------------------------------------------
__global__ void final_kernel(float* __restrict__ out, int N) {
    int i = blockIdx.x * blockDim.x + threadIdx.x;
    if (i >= N) return;
    float4 acc0 = g_acc[2 * i];
    float4 acc1 = g_acc[2 * i + 1];
    float Z    = acc0.x;
    float sumL = acc0.y;
    float q0 = acc0.z, q1 = acc0.w, q2 = acc1.x, q3 = acc1.y;

    float invZ = 1.0f / Z;
    float o0 = q0 * invZ, o1 = q1 * invZ, o2 = q2 * invZ, o3 = q3 * invZ;
    float nrm = sqrtf(o0 * o0 + o1 * o1 + o2 * o2 + o3 * o3);
    nrm = fmaxf(nrm, 1e-12f);
    float inv = 1.0f / nrm;

    float4* outq = (float4*)out;
    outq[i] = make_float4(o0 * inv, o1 * inv, o2 * inv, o3 * inv);
    out[4 * N + i] = sumL * invZ;
}

extern "C" void kernel_launch(void* const* d_in, const int* in_sizes, int n_in,
                              void* d_out, int out_size) {
    const float*  node_levels = (const float*)d_in[0];
    const float4* node_q      = (const float4*)d_in[1];
    const float4* edge_rel_q  = (const float4*)d_in[2];
    const float*  edge_w      = (const float*)d_in[3];
    const int*    src         = (const int*)d_in[4];
    const int*    dst         = (const int*)d_in[5];

    int N = in_sizes[0];          // node count
    int E = in_sizes[3];          // edge count (edge_w element count)

    float* out = (float*)d_out;

    const int T = 256;
    init_kernel<<<(N + T - 1) / T, T>>>(node_levels, node_q, N);
    edge_kernel<<<(E + T - 1) / T, T>>>(node_levels, node_q, edge_rel_q,
                                        edge_w, src, dst, E);
    final_kernel<<<(N + T - 1) / T, T>>>(out, N);
}

// round 3
// speedup vs baseline: 1.9326x; 1.9326x over previous
#include <cuda_runtime.h>
#include <math.h>

// N = 100000 nodes, E = 3200000 edges.
// Per-node accumulator: 8 floats (32B): [Z, sumL, q0, q1, q2, q3, pad, pad]
// Zero-invariant: g_acc is zeroed at module load; final_kernel re-zeroes after
// reading, so every kernel_launch call starts from zeros (graph-replay safe).
#define MAXN 131072
__device__ float4 g_acc[MAXN * 2];

#define TEMP 10.0f

// ---------------------------------------------------------------------------
// Edge scatter: accu_q = qmul(rel_q, q_src); ex = exp(TEMP*w*l_src)
// Accumulate (ex, ex*l, ex*accu_q) into g_acc[dst] with TWO vector REDs
// (v4 + v2) instead of six scalar atomics. Logits bounded in [0,10) so the
// stable-softmax max subtraction cancels exactly and is omitted.
// ---------------------------------------------------------------------------
__global__ void __launch_bounds__(256) edge_kernel(
    const float* __restrict__ node_levels,
    const float4* __restrict__ node_q,
    const float4* __restrict__ edge_rel_q,
    const float* __restrict__ edge_w,
    const int* __restrict__ src,
    const int* __restrict__ dst,
    int E) {
    int e = blockIdx.x * blockDim.x + threadIdx.x;
    if (e >= E) return;

    int s = __ldg(&src[e]);
    int d = __ldg(&dst[e]);
    float4 a = __ldg(&edge_rel_q[e]);   // rel_q components (w,x,y,z)
    float w  = __ldg(&edge_w[e]);

    float4 b = __ldg(&node_q[s]);       // q_src
    float l  = __ldg(&node_levels[s]);

    // Hamilton product rel_q * q_src
    float aw = a.x, ax = a.y, ay = a.z, az = a.w;
    float bw = b.x, bx = b.y, by = b.z, bz = b.w;
    float cw = aw * bw - ax * bx - ay * by - az * bz;
    float cx = aw * bx + ax * bw + ay * bz - az * by;
    float cy = aw * by - ax * bz + ay * bw + az * bx;
    float cz = aw * bz + ax * by - ay * bx + az * bw;

    float ex = __expf(TEMP * w * l);

    float* acc = (float*)&g_acc[2 * d];
    // v4 RED: {Z, sumL, q0, q1} at offset 0 (16B aligned)
    asm volatile("red.global.add.v4.f32 [%0], {%1, %2, %3, %4};"
                 :: "l"(acc), "f"(ex), "f"(ex * l), "f"(ex * cw), "f"(ex * cx)
                 : "memory");
    // v2 RED: {q2, q3} at offset 16 (8B aligned)
    asm volatile("red.global.add.v2.f32 [%0], {%1, %2};"
                 :: "l"(acc + 4), "f"(ex * cy), "f"(ex * cz)
                 : "memory");
}

// ---------------------------------------------------------------------------
// Finalize: add the self term (es = exp(TEMP*l), weight on own q/l), divide
// by Z, L2-normalize the quaternion, write output, and RE-ZERO g_acc to
// restore the zero-invariant for the next replay.
// Output layout: out[0..4N) = out_q row-major, out[4N..5N) = out_levels.
// ---------------------------------------------------------------------------
__global__ void __launch_bounds__(256) final_kernel(
    const float* __restrict__ node_levels,
    const float4* __restrict__ node_q,
    float* __restrict__ out, int N) {
    int i = blockIdx.x * blockDim.x + threadIdx.x;
    if (i >= N) return;

    float4 acc0 = g_acc[2 * i];
    float4 acc1 = g_acc[2 * i + 1];
    // restore zero-invariant
    g_acc[2 * i]     = make_float4(0.f, 0.f, 0.f, 0.f);
    g_acc[2 * i + 1] = make_float4(0.f, 0.f, 0.f, 0.f);

    float l = node_levels[i];
    float4 q = node_q[i];
    float es = __expf(TEMP * l);

    float Z    = acc0.x + es;
    float sumL = acc0.y + es * l;
    float q0 = acc0.z + es * q.x;
    float q1 = acc0.w + es * q.y;
    float q2 = acc1.x + es * q.z;
    float q3 = acc1.y + es * q.w;

    float invZ = 1.0f / Z;
    float o0 = q0 * invZ, o1 = q1 * invZ, o2 = q2 * invZ, o3 = q3 * invZ;
    float nrm = sqrtf(o0 * o0 + o1 * o1 + o2 * o2 + o3 * o3);
    nrm = fmaxf(nrm, 1e-12f);
    float inv = 1.0f / nrm;

    float4* outq = (float4*)out;
    outq[i] = make_float4(o0 * inv, o1 * inv, o2 * inv, o3 * inv);
    out[4 * N + i] = sumL * invZ;
}

extern "C" void kernel_launch(void* const* d_in, const int* in_sizes, int n_in,
                              void* d_out, int out_size) {
    const float*  node_levels = (const float*)d_in[0];
    const float4* node_q      = (const float4*)d_in[1];
    const float4* edge_rel_q  = (const float4*)d_in[2];
    const float*  edge_w      = (const float*)d_in[3];
    const int*    src         = (const int*)d_in[4];
    const int*    dst         = (const int*)d_in[5];

    int N = in_sizes[0];
    int E = in_sizes[3];

    float* out = (float*)d_out;

    const int T = 256;
    edge_kernel<<<(E + T - 1) / T, T>>>(node_levels, node_q, edge_rel_q,
                                        edge_w, src, dst, E);
    final_kernel<<<(N + T - 1) / T, T>>>(node_levels, node_q, out, N);
}